// round 1
// baseline (speedup 1.0000x reference)
#include <cuda_runtime.h>
#include <cstdint>

// Problem shape (fixed by the dataset)
#define NG    4
#define MPTS  50000
#define CIN   64
#define KNN   9
#define OUTC  64
// in_width = (CIN+2)*KNN + CIN = 658
// x layout per neighbor k: rows k*66+0 (locx), k*66+1 (locy), k*66+2..k*66+65 (feats)
// then center feats at rows 594..657.

// Tiling
#define BM       128          // points per block
#define NTHREADS 256          // 8 warps, each warp = 16 rows x 64 cols
#define SA       68           // A smem stride (floats)  -> conflict-free a-frag
#define SW       72           // W smem stride (floats)  -> conflict-free b-frag

// Round-to-nearest tf32 (unbiased; raw truncation would bias output by ~ -1e-3)
__device__ __forceinline__ float tf32r(float x) {
    uint32_t u;
    asm("cvt.rna.tf32.f32 %0, %1;" : "=r"(u) : "f"(x));
    return __uint_as_float(u);
}

__device__ __forceinline__ void mma_tf32(float d[4],
                                         uint32_t a0, uint32_t a1, uint32_t a2, uint32_t a3,
                                         uint32_t b0, uint32_t b1) {
    asm volatile(
        "mma.sync.aligned.m16n8k8.row.col.f32.tf32.tf32.f32 "
        "{%0,%1,%2,%3}, {%4,%5,%6,%7}, {%8,%9}, {%0,%1,%2,%3};"
        : "+f"(d[0]), "+f"(d[1]), "+f"(d[2]), "+f"(d[3])
        : "r"(a0), "r"(a1), "r"(a2), "r"(a3), "r"(b0), "r"(b1));
}

extern "C" __global__ void __launch_bounds__(NTHREADS)
affconv_kernel(const float* __restrict__ feats,
               const int*   __restrict__ aff,
               const float* __restrict__ locs,
               const float* __restrict__ Wt,
               const float* __restrict__ bias,
               float*       __restrict__ out)
{
    extern __shared__ float smem[];
    float* sA   = smem;                         // BM * SA floats (34816 B)
    float* sW   = sA + BM * SA;                 // 64 * SW floats (18432 B)
    int*   sIdx = (int*)(sW + 64 * SW);         // BM * KNN ints  (4608 B)
    float* sB   = (float*)(sIdx + BM * KNN);    // OUTC floats    (256 B)

    const int g    = blockIdx.y;
    const int m0   = blockIdx.x * BM;
    const int tid  = threadIdx.x;
    const int lane = tid & 31;
    const int wid  = tid >> 5;

    const float* F = feats + (size_t)g * MPTS * CIN;
    const int*   I = aff   + (size_t)g * MPTS * KNN;
    const float* L = locs  + (size_t)g * MPTS * 2;
    float*       O = out   + (size_t)g * MPTS * OUTC;

    // ---- stage neighbor indices + bias ----
    for (int i = tid; i < BM * KNN; i += NTHREADS) {
        int r = i / KNN, c = i - r * KNN;
        int m = m0 + r; if (m >= MPTS) m = MPTS - 1;   // clamp partial tile
        sIdx[i] = I[(size_t)m * KNN + c];
    }
    if (tid < OUTC) sB[tid] = bias[tid];
    __syncthreads();

    float acc[8][4];
    #pragma unroll
    for (int nt = 0; nt < 8; nt++)
        acc[nt][0] = acc[nt][1] = acc[nt][2] = acc[nt][3] = 0.f;

    const int wrow = wid * 16;       // warp's row base in the 128-row tile
    const int gq   = lane >> 2;      // 0..7
    const int gr   = lane & 3;       // 0..3

    // 11 K-chunks: 0..8 = gathered neighbor feats (K=64), 9 = center feats (K=64),
    //              10 = loc terms (K=24, rows 18..23 zero)
    for (int chunk = 0; chunk < 11; chunk++) {
        if (chunk < 10) {
            // ---- stage A tile: 128 rows x 64 feats, gathered ----
            {
                int r = tid >> 1, hf = tid & 1;
                int m = m0 + r; if (m >= MPTS) m = MPTS - 1;
                int src = (chunk < 9) ? sIdx[r * KNN + chunk] : m;
                const float4* s4 = (const float4*)(F + (size_t)src * CIN + hf * 32);
                float* dst = sA + r * SA + hf * 32;
                #pragma unroll
                for (int i = 0; i < 8; i++) {
                    float4 v = s4[i];
                    v.x = tf32r(v.x); v.y = tf32r(v.y);
                    v.z = tf32r(v.z); v.w = tf32r(v.w);
                    *(float4*)(dst + i * 4) = v;
                }
            }
            // ---- stage W chunk: 64 rows x 64 cols ----
            {
                int row = tid >> 2, q = tid & 3;
                int rbase = (chunk < 9) ? (chunk * 66 + 2) : 594;
                const float4* s4 = (const float4*)(Wt + (size_t)(rbase + row) * OUTC + q * 16);
                float* dst = sW + row * SW + q * 16;
                #pragma unroll
                for (int i = 0; i < 4; i++) {
                    float4 v = s4[i];
                    v.x = tf32r(v.x); v.y = tf32r(v.y);
                    v.z = tf32r(v.z); v.w = tf32r(v.w);
                    *(float4*)(dst + i * 4) = v;
                }
            }
        } else {
            // ---- loc chunk ----
            if (tid < BM) {
                int r = tid;
                int m = m0 + r; if (m >= MPTS) m = MPTS - 1;
                float lx = L[(size_t)m * 2 + 0];
                float ly = L[(size_t)m * 2 + 1];
                float* dst = sA + r * SA;
                #pragma unroll
                for (int k = 0; k < KNN; k++) {
                    int src = sIdx[r * KNN + k];
                    float dx = (L[(size_t)src * 2 + 0] - lx) / 11.0f;
                    float dy = (L[(size_t)src * 2 + 1] - ly) / 11.0f;
                    dx = fminf(fmaxf(dx, -1.f), 1.f);
                    dy = fminf(fmaxf(dy, -1.f), 1.f);
                    dst[2 * k + 0] = tf32r(dx);
                    dst[2 * k + 1] = tf32r(dy);
                }
                #pragma unroll
                for (int j = 18; j < 24; j++) dst[j] = 0.f;
            } else {
                // threads 128..255 stage W_loc rows (interleaved locx/locy rows), zero-pad 18..23
                for (int i = tid - BM; i < 24 * 16; i += NTHREADS - BM) {
                    int j = i >> 4, q = i & 15;
                    float4 v = make_float4(0.f, 0.f, 0.f, 0.f);
                    if (j < 18) {
                        int wr = (j >> 1) * 66 + (j & 1);
                        v = *(const float4*)(Wt + (size_t)wr * OUTC + q * 4);
                        v.x = tf32r(v.x); v.y = tf32r(v.y);
                        v.z = tf32r(v.z); v.w = tf32r(v.w);
                    }
                    *(float4*)(sW + j * SW + q * 4) = v;
                }
            }
        }
        __syncthreads();

        // ---- MMA over this chunk ----
        const int ksteps = (chunk < 10) ? 8 : 3;
        for (int ks = 0; ks < ksteps; ks++) {
            const int k0 = ks * 8;
            const float* Ab = sA + (wrow + gq) * SA + k0 + gr;
            uint32_t a0 = __float_as_uint(Ab[0]);
            uint32_t a1 = __float_as_uint(Ab[8 * SA]);
            uint32_t a2 = __float_as_uint(Ab[4]);
            uint32_t a3 = __float_as_uint(Ab[8 * SA + 4]);
            const float* Bb = sW + (k0 + gr) * SW + gq;
            #pragma unroll
            for (int nt = 0; nt < 8; nt++) {
                uint32_t b0 = __float_as_uint(Bb[nt * 8]);
                uint32_t b1 = __float_as_uint(Bb[nt * 8 + 4 * SW]);
                mma_tf32(acc[nt], a0, a1, a2, a3, b0, b1);
            }
        }
        __syncthreads();
    }

    // ---- epilogue: accumulators -> smem, then coalesced global stores ----
    #pragma unroll
    for (int nt = 0; nt < 8; nt++) {
        int col = nt * 8 + gr * 2;
        int r0  = wrow + gq;
        sA[r0 * SA + col]           = acc[nt][0];
        sA[r0 * SA + col + 1]       = acc[nt][1];
        sA[(r0 + 8) * SA + col]     = acc[nt][2];
        sA[(r0 + 8) * SA + col + 1] = acc[nt][3];
    }
    __syncthreads();

    for (int r = wid; r < BM; r += 8) {
        int m = m0 + r;
        if (m < MPTS) {
            float v0 = fmaxf(sA[r * SA + lane]      + sB[lane],      0.f);
            float v1 = fmaxf(sA[r * SA + lane + 32] + sB[lane + 32], 0.f);
            O[(size_t)m * OUTC + lane]      = v0;
            O[(size_t)m * OUTC + lane + 32] = v1;
        }
    }
}

extern "C" void kernel_launch(void* const* d_in, const int* in_sizes, int n_in,
                              void* d_out, int out_size)
{
    const float* feats = (const float*)d_in[0];
    const int*   aff   = (const int*)  d_in[1];
    const float* locs  = (const float*)d_in[2];
    const float* Wt    = (const float*)d_in[3];
    const float* bias  = (const float*)d_in[4];
    float*       out   = (float*)d_out;

    const int smem_bytes = (BM * SA + 64 * SW + OUTC) * 4 + BM * KNN * 4;  // 58112 B
    cudaFuncSetAttribute(affconv_kernel,
                         cudaFuncAttributeMaxDynamicSharedMemorySize, smem_bytes);

    dim3 grid((MPTS + BM - 1) / BM, NG);
    affconv_kernel<<<grid, NTHREADS, smem_bytes>>>(feats, aff, locs, Wt, bias, out);
}

// round 3
// speedup vs baseline: 1.2047x; 1.2047x over previous
#include <cuda_runtime.h>
#include <cstdint>

#define NG    4
#define MPTS  50000
#define CIN   64
#define KNN   9
#define OUTC  64
#define BM    128
#define NTH   256
#define NCHUNK 11

// smem layout (bytes)
#define SA_STRIDE 272                    // 68 floats per A row -> conflict-free frags
#define A_BYTES   (BM * SA_STRIDE)       // 34816
#define W_BYTES   16384                  // one chunk of pre-swizzled W frags
#define OFF_A0    0
#define OFF_A1    A_BYTES
#define OFF_W0    (2 * A_BYTES)
#define OFF_W1    (2 * A_BYTES + W_BYTES)
#define OFF_IDX   (2 * A_BYTES + 2 * W_BYTES)
#define SMEM_MAIN (OFF_IDX + BM * KNN * 4)   // 107008 B -> 2 blocks/SM

// ---- persistent scratch (allocation-free rule: __device__ globals) ----
__device__ float  g_featsC[(size_t)NG * MPTS * CIN];   // tf32-rna converted feats
__device__ float  g_locF[(size_t)NG * MPTS * 24];      // precomputed loc features (padded)
__device__ float2 g_fragW[NCHUNK * 2048];              // W in b-fragment order

__device__ __forceinline__ float tf32r(float x) {
    uint32_t u;
    asm("cvt.rna.tf32.f32 %0, %1;" : "=r"(u) : "f"(x));
    return __uint_as_float(u);
}

__device__ __forceinline__ uint32_t smem_u32(const void* p) {
    uint32_t a;
    asm("{ .reg .u64 t; cvta.to.shared.u64 t, %1; cvt.u32.u64 %0, t; }" : "=r"(a) : "l"(p));
    return a;
}

__device__ __forceinline__ void cpa16(uint32_t dst, const void* src) {
    uint64_t gp = __cvta_generic_to_global(src);
    asm volatile("cp.async.cg.shared.global [%0], [%1], 16;" :: "r"(dst), "l"(gp));
}

__device__ __forceinline__ void mma_tf32(float d[4],
                                         uint32_t a0, uint32_t a1, uint32_t a2, uint32_t a3,
                                         uint32_t b0, uint32_t b1) {
    asm volatile(
        "mma.sync.aligned.m16n8k8.row.col.f32.tf32.tf32.f32 "
        "{%0,%1,%2,%3}, {%4,%5,%6,%7}, {%8,%9}, {%0,%1,%2,%3};"
        : "+f"(d[0]), "+f"(d[1]), "+f"(d[2]), "+f"(d[3])
        : "r"(a0), "r"(a1), "r"(a2), "r"(a3), "r"(b0), "r"(b1));
}

// ---------------- pre-pass kernels ----------------

__global__ void __launch_bounds__(NTH) k_convert(const float* __restrict__ feats) {
    size_t i = ((size_t)blockIdx.x * NTH + threadIdx.x) * 4;
    if (i < (size_t)NG * MPTS * CIN) {
        float4 v = *(const float4*)(feats + i);
        v.x = tf32r(v.x); v.y = tf32r(v.y); v.z = tf32r(v.z); v.w = tf32r(v.w);
        *(float4*)(g_featsC + i) = v;
    }
}

__global__ void __launch_bounds__(NTH) k_locfeat(const int* __restrict__ aff,
                                                 const float* __restrict__ locs) {
    int t = blockIdx.x * NTH + threadIdx.x;
    if (t >= NG * MPTS) return;
    int g = t / MPTS, m = t - g * MPTS;
    const int*   I = aff  + (size_t)g * MPTS * KNN + (size_t)m * KNN;
    const float* L = locs + (size_t)g * MPTS * 2;
    float lx = L[2 * m], ly = L[2 * m + 1];
    float o[24];
    #pragma unroll
    for (int j = 18; j < 24; j++) o[j] = 0.f;
    #pragma unroll
    for (int k = 0; k < KNN; k++) {
        int s = I[k];
        float dx = (L[2 * s]     - lx) * (1.0f / 11.0f);
        float dy = (L[2 * s + 1] - ly) * (1.0f / 11.0f);
        o[2 * k]     = tf32r(fminf(fmaxf(dx, -1.f), 1.f));
        o[2 * k + 1] = tf32r(fminf(fmaxf(dy, -1.f), 1.f));
    }
    float4* d = (float4*)(g_locF + (size_t)t * 24);
    #pragma unroll
    for (int j = 0; j < 6; j++)
        d[j] = make_float4(o[4*j], o[4*j+1], o[4*j+2], o[4*j+3]);
}

__global__ void __launch_bounds__(NTH) k_fragW(const float* __restrict__ Wt) {
    int t = blockIdx.x * NTH + threadIdx.x;
    if (t >= NCHUNK * 2048) return;
    int c = t / 2048, rem = t % 2048;
    int nt = rem >> 8, ks = (rem >> 5) & 7, ln = rem & 31;
    int gq = ln >> 2, gr = ln & 3;
    int col = nt * 8 + gq;
    int k0 = ks * 8 + gr;
    int k1 = k0 + 4;
    auto krow = [&](int k) -> int {
        if (c < 9)  return c * 66 + 2 + k;
        if (c == 9) return 594 + k;
        return (k < 18) ? (k >> 1) * 66 + (k & 1) : -1;   // loc chunk, zero-padded
    };
    int r0 = krow(k0), r1 = krow(k1);
    float v0 = (r0 >= 0) ? tf32r(Wt[(size_t)r0 * OUTC + col]) : 0.f;
    float v1 = (r1 >= 0) ? tf32r(Wt[(size_t)r1 * OUTC + col]) : 0.f;
    g_fragW[t] = make_float2(v0, v1);
}

// ---------------- main kernel ----------------

extern "C" __global__ void __launch_bounds__(NTH, 2)
affconv_main(const int* __restrict__ aff,
             const float* __restrict__ bias,
             float* __restrict__ out)
{
    extern __shared__ char smem[];
    const uint32_t sbase = smem_u32(smem);
    const int tid = threadIdx.x, lane = tid & 31, wid = tid >> 5;
    const int g = blockIdx.y, m0 = blockIdx.x * BM;
    const int gq = lane >> 2, gr = lane & 3;
    const int wr = wid >> 1, wc = wid & 1;          // 4x2 warp grid: 32 rows x 32 cols

    int* sIdx = (int*)(smem + OFF_IDX);
    const int* I = aff + (size_t)g * MPTS * KNN;

    for (int i = tid; i < BM * KNN; i += NTH) {
        int r = i / KNN, c = i - r * KNN;
        int m = m0 + r; if (m >= MPTS) m = MPTS - 1;
        sIdx[i] = I[(size_t)m * KNN + c];
    }
    __syncthreads();

    const int r_ = tid >> 1, h_ = tid & 1;
    int m_ = m0 + r_; if (m_ >= MPTS) m_ = MPTS - 1;
    const float* featG = g_featsC + (size_t)g * MPTS * CIN;
    const float* locG  = g_locF   + (size_t)g * MPTS * 24;

    auto stage = [&](int c, int buf) {
        uint32_t aDst = sbase + (buf ? OFF_A1 : OFF_A0) + r_ * SA_STRIDE;
        if (c < 10) {
            int src = (c < 9) ? sIdx[r_ * KNN + c] : m_;
            const char* s = (const char*)(featG + (size_t)src * CIN + h_ * 32);
            uint32_t d = aDst + h_ * 128;
            #pragma unroll
            for (int j = 0; j < 8; j++) cpa16(d + j * 16, s + j * 16);
        } else if (h_ == 0) {
            const char* s = (const char*)(locG + (size_t)m_ * 24);
            #pragma unroll
            for (int j = 0; j < 6; j++) cpa16(aDst + j * 16, s + j * 16);
        }
        uint32_t wDst = sbase + (buf ? OFF_W1 : OFF_W0) + tid * 64;
        const char* ws = (const char*)(g_fragW + c * 2048) + tid * 64;
        #pragma unroll
        for (int j = 0; j < 4; j++) cpa16(wDst + j * 16, ws + j * 16);
        asm volatile("cp.async.commit_group;" ::: "memory");
    };

    float acc[2][4][4];
    #pragma unroll
    for (int a = 0; a < 2; a++)
        #pragma unroll
        for (int b = 0; b < 4; b++)
            acc[a][b][0] = acc[a][b][1] = acc[a][b][2] = acc[a][b][3] = 0.f;

    stage(0, 0);

    for (int c = 0; c < NCHUNK; c++) {
        if (c + 1 < NCHUNK) {
            stage(c + 1, (c + 1) & 1);
            asm volatile("cp.async.wait_group 1;" ::: "memory");
        } else {
            asm volatile("cp.async.wait_group 0;" ::: "memory");
        }
        __syncthreads();

        const char* A  = smem + ((c & 1) ? OFF_A1 : OFF_A0);
        const char* Wb = smem + ((c & 1) ? OFF_W1 : OFF_W0);
        const char* aBase = A + (wr * 32 + gq) * SA_STRIDE + gr * 4;
        const float2* bP  = (const float2*)Wb + (wc * 4 * 8) * 32 + lane;

        auto mmaks = [&](int ks) {
            const char* ab = aBase + ks * 32;
            uint32_t a00 = *(const uint32_t*)(ab);
            uint32_t a01 = *(const uint32_t*)(ab + 8 * SA_STRIDE);
            uint32_t a02 = *(const uint32_t*)(ab + 16);
            uint32_t a03 = *(const uint32_t*)(ab + 8 * SA_STRIDE + 16);
            const char* ab1 = ab + 16 * SA_STRIDE;
            uint32_t a10 = *(const uint32_t*)(ab1);
            uint32_t a11 = *(const uint32_t*)(ab1 + 8 * SA_STRIDE);
            uint32_t a12 = *(const uint32_t*)(ab1 + 16);
            uint32_t a13 = *(const uint32_t*)(ab1 + 8 * SA_STRIDE + 16);
            #pragma unroll
            for (int nt = 0; nt < 4; nt++) {
                float2 b = bP[(nt * 8 + ks) * 32];
                uint32_t b0 = __float_as_uint(b.x), b1 = __float_as_uint(b.y);
                mma_tf32(acc[0][nt], a00, a01, a02, a03, b0, b1);
                mma_tf32(acc[1][nt], a10, a11, a12, a13, b0, b1);
            }
        };

        if (c < 10) {
            #pragma unroll
            for (int ks = 0; ks < 8; ks++) mmaks(ks);
        } else {
            mmaks(0); mmaks(1); mmaks(2);
        }
        __syncthreads();
    }

    // ---- epilogue: bounce through smem for coalesced stores ----
    float* sO = (float*)smem;                     // reuse buffer A0, stride 68 floats
    #pragma unroll
    for (int rg = 0; rg < 2; rg++) {
        #pragma unroll
        for (int nt = 0; nt < 4; nt++) {
            int row = wr * 32 + rg * 16 + gq;
            int col = wc * 32 + nt * 8 + gr * 2;
            sO[row * 68 + col]           = acc[rg][nt][0];
            sO[row * 68 + col + 1]       = acc[rg][nt][1];
            sO[(row + 8) * 68 + col]     = acc[rg][nt][2];
            sO[(row + 8) * 68 + col + 1] = acc[rg][nt][3];
        }
    }
    __syncthreads();

    float2 bb = *(const float2*)(bias + lane * 2);
    float* O = out + (size_t)g * MPTS * OUTC;
    for (int r = wid; r < BM; r += 8) {
        int m = m0 + r;
        if (m < MPTS) {
            float2 v = *(float2*)(sO + r * 68 + lane * 2);
            v.x = fmaxf(v.x + bb.x, 0.f);
            v.y = fmaxf(v.y + bb.y, 0.f);
            *(float2*)(O + (size_t)m * OUTC + lane * 2) = v;
        }
    }
}

extern "C" void kernel_launch(void* const* d_in, const int* in_sizes, int n_in,
                              void* d_out, int out_size)
{
    const float* feats = (const float*)d_in[0];
    const int*   aff   = (const int*)  d_in[1];
    const float* locs  = (const float*)d_in[2];
    const float* Wt    = (const float*)d_in[3];
    const float* bias  = (const float*)d_in[4];
    float*       out   = (float*)d_out;

    k_convert<<<(NG * MPTS * CIN / 4 + NTH - 1) / NTH, NTH>>>(feats);
    k_locfeat<<<(NG * MPTS + NTH - 1) / NTH, NTH>>>(aff, locs);
    k_fragW<<<(NCHUNK * 2048 + NTH - 1) / NTH, NTH>>>(Wt);

    cudaFuncSetAttribute(affconv_main,
                         cudaFuncAttributeMaxDynamicSharedMemorySize, SMEM_MAIN);
    dim3 grid((MPTS + BM - 1) / BM, NG);
    affconv_main<<<grid, NTH, SMEM_MAIN>>>(aff, bias, out);
}

// round 4
// speedup vs baseline: 1.2812x; 1.0635x over previous
#include <cuda_runtime.h>
#include <cstdint>

#define NG    4
#define MPTS  50000
#define CIN   64
#define KNN   9
#define OUTC  64
#define BM    128
#define NTH   256
#define NCHUNK 11

// smem: two A buffers (swizzled, 256 B/row) + neighbor indices
#define A_BYTES   (BM * 256)                 // 32768
#define OFF_A0    0
#define OFF_A1    A_BYTES
#define OFF_IDX   (2 * A_BYTES)              // 65536
#define SMEM_MAIN (OFF_IDX + BM * KNN * 4)   // 70144 B -> 3 CTAs/SM

// ---- persistent scratch ----
__device__ float  g_featsC[(size_t)NG * MPTS * CIN];   // tf32-rna feats
__device__ float  g_locF[(size_t)NG * MPTS * 24];      // precomputed loc features
__device__ float2 g_fragW[NCHUNK * 2048];              // W in b-fragment order

__device__ __forceinline__ float tf32r(float x) {
    uint32_t u;
    asm("cvt.rna.tf32.f32 %0, %1;" : "=r"(u) : "f"(x));
    return __uint_as_float(u);
}
__device__ __forceinline__ uint32_t smem_u32(const void* p) {
    uint32_t a;
    asm("{ .reg .u64 t; cvta.to.shared.u64 t, %1; cvt.u32.u64 %0, t; }" : "=r"(a) : "l"(p));
    return a;
}
__device__ __forceinline__ void cpa16(uint32_t dst, const void* src) {
    uint64_t gp = __cvta_generic_to_global(src);
    asm volatile("cp.async.cg.shared.global [%0], [%1], 16;" :: "r"(dst), "l"(gp));
}
__device__ __forceinline__ void mma_tf32(float d[4],
                                         uint32_t a0, uint32_t a1, uint32_t a2, uint32_t a3,
                                         uint32_t b0, uint32_t b1) {
    asm volatile(
        "mma.sync.aligned.m16n8k8.row.col.f32.tf32.tf32.f32 "
        "{%0,%1,%2,%3}, {%4,%5,%6,%7}, {%8,%9}, {%0,%1,%2,%3};"
        : "+f"(d[0]), "+f"(d[1]), "+f"(d[2]), "+f"(d[3])
        : "r"(a0), "r"(a1), "r"(a2), "r"(a3), "r"(b0), "r"(b1));
}

// ---------------- pre-pass kernels ----------------

__global__ void __launch_bounds__(NTH) k_convert(const float* __restrict__ feats) {
    size_t i = ((size_t)blockIdx.x * NTH + threadIdx.x) * 4;
    if (i < (size_t)NG * MPTS * CIN) {
        float4 v = *(const float4*)(feats + i);
        v.x = tf32r(v.x); v.y = tf32r(v.y); v.z = tf32r(v.z); v.w = tf32r(v.w);
        *(float4*)(g_featsC + i) = v;
    }
}

__global__ void __launch_bounds__(NTH) k_locfeat(const int* __restrict__ aff,
                                                 const float* __restrict__ locs) {
    int t = blockIdx.x * NTH + threadIdx.x;
    if (t >= NG * MPTS) return;
    int g = t / MPTS, m = t - g * MPTS;
    const int*   I = aff  + (size_t)g * MPTS * KNN + (size_t)m * KNN;
    const float* L = locs + (size_t)g * MPTS * 2;
    float lx = L[2 * m], ly = L[2 * m + 1];
    float o[24];
    #pragma unroll
    for (int j = 18; j < 24; j++) o[j] = 0.f;
    #pragma unroll
    for (int k = 0; k < KNN; k++) {
        int s = I[k];
        float dx = (L[2 * s]     - lx) * (1.0f / 11.0f);
        float dy = (L[2 * s + 1] - ly) * (1.0f / 11.0f);
        o[2 * k]     = tf32r(fminf(fmaxf(dx, -1.f), 1.f));
        o[2 * k + 1] = tf32r(fminf(fmaxf(dy, -1.f), 1.f));
    }
    float4* d = (float4*)(g_locF + (size_t)t * 24);
    #pragma unroll
    for (int j = 0; j < 6; j++)
        d[j] = make_float4(o[4*j], o[4*j+1], o[4*j+2], o[4*j+3]);
}

__global__ void __launch_bounds__(NTH) k_fragW(const float* __restrict__ Wt) {
    int t = blockIdx.x * NTH + threadIdx.x;
    if (t >= NCHUNK * 2048) return;
    int c = t / 2048, rem = t % 2048;
    int nt = rem >> 8, ks = (rem >> 5) & 7, ln = rem & 31;
    int gq = ln >> 2, gr = ln & 3;
    int col = nt * 8 + gq;
    int k0 = ks * 8 + gr;
    int k1 = k0 + 4;
    auto krow = [&](int k) -> int {
        if (c < 9)  return c * 66 + 2 + k;
        if (c == 9) return 594 + k;
        return (k < 18) ? (k >> 1) * 66 + (k & 1) : -1;
    };
    int r0 = krow(k0), r1 = krow(k1);
    float v0 = (r0 >= 0) ? tf32r(Wt[(size_t)r0 * OUTC + col]) : 0.f;
    float v1 = (r1 >= 0) ? tf32r(Wt[(size_t)r1 * OUTC + col]) : 0.f;
    g_fragW[t] = make_float2(v0, v1);
}

// ---------------- main kernel ----------------

extern "C" __global__ void __launch_bounds__(NTH, 3)
affconv_main(const int* __restrict__ aff,
             const float* __restrict__ bias,
             float* __restrict__ out)
{
    extern __shared__ char smem[];
    const uint32_t sbase = smem_u32(smem);
    const int tid = threadIdx.x, lane = tid & 31, wid = tid >> 5;
    const int g = blockIdx.y, m0 = blockIdx.x * BM;
    const int gq = lane >> 2, gr = lane & 3;
    const int wr = wid >> 1, wc = wid & 1;          // 4x2 warp grid

    int* sIdx = (int*)(smem + OFF_IDX);
    const int* I = aff + (size_t)g * MPTS * KNN;

    for (int i = tid; i < BM * KNN; i += NTH) {
        int r = i / KNN, c = i - r * KNN;
        int m = m0 + r; if (m >= MPTS) m = MPTS - 1;
        sIdx[i] = I[(size_t)m * KNN + c];
    }
    __syncthreads();

    const int r_ = tid >> 1, h_ = tid & 1;
    int m_ = m0 + r_; if (m_ >= MPTS) m_ = MPTS - 1;
    const float* featG = g_featsC + (size_t)g * MPTS * CIN;
    const float* locG  = g_locF   + (size_t)g * MPTS * 24;
    const int rsw = r_ & 7;                          // staging swizzle key

    auto stage = [&](int c, int buf) {
        uint32_t aDst = sbase + (buf ? OFF_A1 : OFF_A0) + r_ * 256;
        if (c < 10) {
            int src = (c < 9) ? sIdx[r_ * KNN + c] : m_;
            const char* s = (const char*)(featG + (size_t)src * CIN + h_ * 32);
            #pragma unroll
            for (int j = 0; j < 8; j++)
                cpa16(aDst + (h_ * 8 + (j ^ rsw)) * 16, s + j * 16);
        } else if (h_ == 0) {
            const char* s = (const char*)(locG + (size_t)m_ * 24);
            #pragma unroll
            for (int j = 0; j < 6; j++)
                cpa16(aDst + (j ^ rsw) * 16, s + j * 16);
        }
        asm volatile("cp.async.commit_group;" ::: "memory");
    };

    float acc[2][4][4];
    #pragma unroll
    for (int a = 0; a < 2; a++)
        #pragma unroll
        for (int b = 0; b < 4; b++)
            acc[a][b][0] = acc[a][b][1] = acc[a][b][2] = acc[a][b][3] = 0.f;

    stage(0, 0);

    for (int c = 0; c < NCHUNK; c++) {
        if (c + 1 < NCHUNK) {
            stage(c + 1, (c + 1) & 1);
            asm volatile("cp.async.wait_group 1;" ::: "memory");
        } else {
            asm volatile("cp.async.wait_group 0;" ::: "memory");
        }
        __syncthreads();

        const char* A = smem + ((c & 1) ? OFF_A1 : OFF_A0);
        const char* aRow0 = A + (wr * 32 + gq) * 256 + gr * 4;   // rows: +0,+8,+16,+24 via +2048
        const float2* bG = g_fragW + c * 2048 + wc * 1024 + lane;

        const int ksteps = (c < 10) ? 8 : 3;
        #pragma unroll 4
        for (int ks = 0; ks < ksteps; ks++) {
            const int o0 = (((ks * 2)     ^ gq) << 4);
            const int o1 = (((ks * 2 + 1) ^ gq) << 4);
            uint32_t a00 = *(const uint32_t*)(aRow0 + o0);
            uint32_t a01 = *(const uint32_t*)(aRow0 + 2048 + o0);
            uint32_t a02 = *(const uint32_t*)(aRow0 + o1);
            uint32_t a03 = *(const uint32_t*)(aRow0 + 2048 + o1);
            uint32_t a10 = *(const uint32_t*)(aRow0 + 4096 + o0);
            uint32_t a11 = *(const uint32_t*)(aRow0 + 6144 + o0);
            uint32_t a12 = *(const uint32_t*)(aRow0 + 4096 + o1);
            uint32_t a13 = *(const uint32_t*)(aRow0 + 6144 + o1);
            #pragma unroll
            for (int nt = 0; nt < 4; nt++) {
                float2 b = __ldg(bG + (nt * 8 + ks) * 32);
                uint32_t b0 = __float_as_uint(b.x), b1 = __float_as_uint(b.y);
                mma_tf32(acc[0][nt], a00, a01, a02, a03, b0, b1);
                mma_tf32(acc[1][nt], a10, a11, a12, a13, b0, b1);
            }
        }
        __syncthreads();
    }

    // ---- epilogue: bounce through smem (stride 68 floats, fits in A region) ----
    float* sO = (float*)smem;
    #pragma unroll
    for (int rg = 0; rg < 2; rg++) {
        #pragma unroll
        for (int nt = 0; nt < 4; nt++) {
            int row = wr * 32 + rg * 16 + gq;
            int col = wc * 32 + nt * 8 + gr * 2;
            sO[row * 68 + col]           = acc[rg][nt][0];
            sO[row * 68 + col + 1]       = acc[rg][nt][1];
            sO[(row + 8) * 68 + col]     = acc[rg][nt][2];
            sO[(row + 8) * 68 + col + 1] = acc[rg][nt][3];
        }
    }
    __syncthreads();

    float2 bb = *(const float2*)(bias + lane * 2);
    float* O = out + (size_t)g * MPTS * OUTC;
    for (int r = wid; r < BM; r += 8) {
        int m = m0 + r;
        if (m < MPTS) {
            float2 v = *(float2*)(sO + r * 68 + lane * 2);
            v.x = fmaxf(v.x + bb.x, 0.f);
            v.y = fmaxf(v.y + bb.y, 0.f);
            *(float2*)(O + (size_t)m * OUTC + lane * 2) = v;
        }
    }
}

extern "C" void kernel_launch(void* const* d_in, const int* in_sizes, int n_in,
                              void* d_out, int out_size)
{
    const float* feats = (const float*)d_in[0];
    const int*   aff   = (const int*)  d_in[1];
    const float* locs  = (const float*)d_in[2];
    const float* Wt    = (const float*)d_in[3];
    const float* bias  = (const float*)d_in[4];
    float*       out   = (float*)d_out;

    k_convert<<<(NG * MPTS * CIN / 4 + NTH - 1) / NTH, NTH>>>(feats);
    k_locfeat<<<(NG * MPTS + NTH - 1) / NTH, NTH>>>(aff, locs);
    k_fragW<<<(NCHUNK * 2048 + NTH - 1) / NTH, NTH>>>(Wt);

    cudaFuncSetAttribute(affconv_main,
                         cudaFuncAttributeMaxDynamicSharedMemorySize, SMEM_MAIN);
    dim3 grid((MPTS + BM - 1) / BM, NG);
    affconv_main<<<grid, NTH, SMEM_MAIN>>>(aff, bias, out);
}

// round 5
// speedup vs baseline: 1.9724x; 1.5394x over previous
#include <cuda_runtime.h>
#include <cstdint>

#define NG    4
#define MPTS  50000
#define CIN   64
#define KNN   9
#define OUTC  64
#define BM    128
#define NTH   256
#define NCHUNK 11

// smem: two A buffers (272 B/row, conflict-free frags, bulk-copy friendly) + idx + mbars
#define ROWB      272
#define A_BYTES   (BM * ROWB)                // 34816
#define OFF_A0    0
#define OFF_A1    A_BYTES
#define OFF_IDX   (2 * A_BYTES)              // 69632, 4608 B
#define OFF_MBAR  (OFF_IDX + BM * KNN * 4)   // 74240, 16 B
#define SMEM_MAIN (OFF_MBAR + 16)            // 74256 -> 3 CTAs/SM

// ---- persistent scratch ----
__device__ float  g_featsC[(size_t)NG * MPTS * CIN];   // tf32-rna feats
__device__ float  g_locF[(size_t)NG * MPTS * 24];      // precomputed loc features
__device__ float2 g_fragW[NCHUNK * 2048];              // W in b-fragment order

__device__ __forceinline__ float tf32r(float x) {
    uint32_t u;
    asm("cvt.rna.tf32.f32 %0, %1;" : "=r"(u) : "f"(x));
    return __uint_as_float(u);
}
__device__ __forceinline__ uint32_t smem_u32(const void* p) {
    uint32_t a;
    asm("{ .reg .u64 t; cvta.to.shared.u64 t, %1; cvt.u32.u64 %0, t; }" : "=r"(a) : "l"(p));
    return a;
}
__device__ __forceinline__ void mma_tf32(float d[4],
                                         uint32_t a0, uint32_t a1, uint32_t a2, uint32_t a3,
                                         uint32_t b0, uint32_t b1) {
    asm volatile(
        "mma.sync.aligned.m16n8k8.row.col.f32.tf32.tf32.f32 "
        "{%0,%1,%2,%3}, {%4,%5,%6,%7}, {%8,%9}, {%0,%1,%2,%3};"
        : "+f"(d[0]), "+f"(d[1]), "+f"(d[2]), "+f"(d[3])
        : "r"(a0), "r"(a1), "r"(a2), "r"(a3), "r"(b0), "r"(b1));
}
__device__ __forceinline__ void mbar_wait(uint32_t mbar, uint32_t parity) {
    uint32_t done;
    asm volatile(
        "{\n\t.reg .pred p;\n\t"
        "mbarrier.try_wait.parity.acquire.cta.shared::cta.b64 p, [%1], %2;\n\t"
        "selp.b32 %0, 1, 0, p;\n\t}"
        : "=r"(done) : "r"(mbar), "r"(parity) : "memory");
    if (!done) {
        asm volatile(
            "{\n\t.reg .pred P1;\n\t"
            "W_%=:\n\t"
            "mbarrier.try_wait.parity.acquire.cta.shared::cta.b64 P1, [%0], %1, 0x989680;\n\t"
            "@P1 bra.uni D_%=;\n\t"
            "bra.uni W_%=;\n\t"
            "D_%=:\n\t}"
            :: "r"(mbar), "r"(parity) : "memory");
    }
}

// ---------------- pre-pass kernels ----------------

__global__ void __launch_bounds__(NTH) k_convert(const float* __restrict__ feats) {
    size_t i = ((size_t)blockIdx.x * NTH + threadIdx.x) * 4;
    if (i < (size_t)NG * MPTS * CIN) {
        float4 v = *(const float4*)(feats + i);
        v.x = tf32r(v.x); v.y = tf32r(v.y); v.z = tf32r(v.z); v.w = tf32r(v.w);
        *(float4*)(g_featsC + i) = v;
    }
}

__global__ void __launch_bounds__(NTH) k_locfeat(const int* __restrict__ aff,
                                                 const float* __restrict__ locs) {
    int t = blockIdx.x * NTH + threadIdx.x;
    if (t >= NG * MPTS) return;
    int g = t / MPTS, m = t - g * MPTS;
    const int*   I = aff  + (size_t)g * MPTS * KNN + (size_t)m * KNN;
    const float* L = locs + (size_t)g * MPTS * 2;
    float lx = L[2 * m], ly = L[2 * m + 1];
    float o[24];
    #pragma unroll
    for (int j = 18; j < 24; j++) o[j] = 0.f;
    #pragma unroll
    for (int k = 0; k < KNN; k++) {
        int s = I[k];
        float dx = (L[2 * s]     - lx) * (1.0f / 11.0f);
        float dy = (L[2 * s + 1] - ly) * (1.0f / 11.0f);
        o[2 * k]     = tf32r(fminf(fmaxf(dx, -1.f), 1.f));
        o[2 * k + 1] = tf32r(fminf(fmaxf(dy, -1.f), 1.f));
    }
    float4* d = (float4*)(g_locF + (size_t)t * 24);
    #pragma unroll
    for (int j = 0; j < 6; j++)
        d[j] = make_float4(o[4*j], o[4*j+1], o[4*j+2], o[4*j+3]);
}

__global__ void __launch_bounds__(NTH) k_fragW(const float* __restrict__ Wt) {
    int t = blockIdx.x * NTH + threadIdx.x;
    if (t >= NCHUNK * 2048) return;
    int c = t / 2048, rem = t % 2048;
    int nt = rem >> 8, ks = (rem >> 5) & 7, ln = rem & 31;
    int gq = ln >> 2, gr = ln & 3;
    int col = nt * 8 + gq;
    int k0 = ks * 8 + gr;
    int k1 = k0 + 4;
    auto krow = [&](int k) -> int {
        if (c < 9)  return c * 66 + 2 + k;
        if (c == 9) return 594 + k;
        return (k < 18) ? (k >> 1) * 66 + (k & 1) : -1;
    };
    int r0 = krow(k0), r1 = krow(k1);
    float v0 = (r0 >= 0) ? tf32r(Wt[(size_t)r0 * OUTC + col]) : 0.f;
    float v1 = (r1 >= 0) ? tf32r(Wt[(size_t)r1 * OUTC + col]) : 0.f;
    g_fragW[t] = make_float2(v0, v1);
}

// ---------------- main kernel ----------------

extern "C" __global__ void __launch_bounds__(NTH, 3)
affconv_main(const int* __restrict__ aff,
             const float* __restrict__ bias,
             float* __restrict__ out)
{
    extern __shared__ char smem[];
    const uint32_t sbase = smem_u32(smem);
    const int tid = threadIdx.x, lane = tid & 31, wid = tid >> 5;
    const int g = blockIdx.y, m0 = blockIdx.x * BM;
    const int gq = lane >> 2, gr = lane & 3;
    const int wr = wid >> 1, wc = wid & 1;          // 4x2 warp grid

    int* sIdx = (int*)(smem + OFF_IDX);
    const int* I = aff + (size_t)g * MPTS * KNN;

    if (tid == 0) {
        asm volatile("mbarrier.init.shared.b64 [%0], %1;" :: "r"(sbase + OFF_MBAR),     "r"(128u) : "memory");
        asm volatile("mbarrier.init.shared.b64 [%0], %1;" :: "r"(sbase + OFF_MBAR + 8), "r"(128u) : "memory");
    }
    for (int i = tid; i < BM * KNN; i += NTH) {
        int r = i / KNN, c = i - r * KNN;
        int m = m0 + r; if (m >= MPTS) m = MPTS - 1;
        sIdx[i] = I[(size_t)m * KNN + c];
    }
    __syncthreads();

    int mrow = m0 + tid; if (mrow >= MPTS) mrow = MPTS - 1;   // valid for tid<128
    const float* featG = g_featsC + (size_t)g * MPTS * CIN;
    const float* locG  = g_locF   + (size_t)g * MPTS * 24;

    auto stage = [&](int c, int buf) {
        if (tid < BM) {
            uint32_t mbar = sbase + OFF_MBAR + buf * 8;
            uint32_t dst  = sbase + (buf ? OFF_A1 : OFF_A0) + tid * ROWB;
            if (c < 10) {
                asm volatile("mbarrier.arrive.expect_tx.shared.b64 _, [%0], 256;"
                             :: "r"(mbar) : "memory");
                int src = (c < 9) ? sIdx[tid * KNN + c] : mrow;
                uint64_t gp = __cvta_generic_to_global(featG + (size_t)src * CIN);
                asm volatile(
                    "cp.async.bulk.shared::cluster.global.mbarrier::complete_tx::bytes "
                    "[%0], [%1], 256, [%2];"
                    :: "r"(dst), "l"(gp), "r"(mbar) : "memory");
            } else {
                asm volatile("mbarrier.arrive.expect_tx.shared.b64 _, [%0], 96;"
                             :: "r"(mbar) : "memory");
                uint64_t gp = __cvta_generic_to_global(locG + (size_t)mrow * 24);
                asm volatile(
                    "cp.async.bulk.shared::cluster.global.mbarrier::complete_tx::bytes "
                    "[%0], [%1], 96, [%2];"
                    :: "r"(dst), "l"(gp), "r"(mbar) : "memory");
            }
        }
    };

    float acc[2][4][4];
    #pragma unroll
    for (int a = 0; a < 2; a++)
        #pragma unroll
        for (int b = 0; b < 4; b++)
            acc[a][b][0] = acc[a][b][1] = acc[a][b][2] = acc[a][b][3] = 0.f;

    stage(0, 0);

    for (int c = 0; c < NCHUNK; c++) {
        if (c + 1 < NCHUNK) stage(c + 1, (c + 1) & 1);

        // wait for chunk c's bulk copies to land
        mbar_wait(sbase + OFF_MBAR + (c & 1) * 8, (c >> 1) & 1);

        const char* A = smem + ((c & 1) ? OFF_A1 : OFF_A0);
        const char* aRow0 = A + (wr * 32 + gq) * ROWB + gr * 4;
        const float2* bG = g_fragW + c * 2048 + wc * 1024 + lane;

        const int ksteps = (c < 10) ? 8 : 3;
        #pragma unroll 4
        for (int ks = 0; ks < ksteps; ks++) {
            const int o = ks * 32;
            uint32_t a00 = *(const uint32_t*)(aRow0 + o);
            uint32_t a01 = *(const uint32_t*)(aRow0 + 8 * ROWB + o);
            uint32_t a02 = *(const uint32_t*)(aRow0 + o + 16);
            uint32_t a03 = *(const uint32_t*)(aRow0 + 8 * ROWB + o + 16);
            uint32_t a10 = *(const uint32_t*)(aRow0 + 16 * ROWB + o);
            uint32_t a11 = *(const uint32_t*)(aRow0 + 24 * ROWB + o);
            uint32_t a12 = *(const uint32_t*)(aRow0 + 16 * ROWB + o + 16);
            uint32_t a13 = *(const uint32_t*)(aRow0 + 24 * ROWB + o + 16);
            #pragma unroll
            for (int nt = 0; nt < 4; nt++) {
                float2 b = __ldg(bG + (nt * 8 + ks) * 32);
                uint32_t b0 = __float_as_uint(b.x), b1 = __float_as_uint(b.y);
                mma_tf32(acc[0][nt], a00, a01, a02, a03, b0, b1);
                mma_tf32(acc[1][nt], a10, a11, a12, a13, b0, b1);
            }
        }
        __syncthreads();   // all warps done reading buf (c&1) before it is restaged
    }

    // ---- epilogue: bounce through smem (stride 68 floats) ----
    float* sO = (float*)smem;
    #pragma unroll
    for (int rg = 0; rg < 2; rg++) {
        #pragma unroll
        for (int nt = 0; nt < 4; nt++) {
            int row = wr * 32 + rg * 16 + gq;
            int col = wc * 32 + nt * 8 + gr * 2;
            sO[row * 68 + col]           = acc[rg][nt][0];
            sO[row * 68 + col + 1]       = acc[rg][nt][1];
            sO[(row + 8) * 68 + col]     = acc[rg][nt][2];
            sO[(row + 8) * 68 + col + 1] = acc[rg][nt][3];
        }
    }
    __syncthreads();

    float2 bb = *(const float2*)(bias + lane * 2);
    float* O = out + (size_t)g * MPTS * OUTC;
    for (int r = wid; r < BM; r += 8) {
        int m = m0 + r;
        if (m < MPTS) {
            float2 v = *(float2*)(sO + r * 68 + lane * 2);
            v.x = fmaxf(v.x + bb.x, 0.f);
            v.y = fmaxf(v.y + bb.y, 0.f);
            *(float2*)(O + (size_t)m * OUTC + lane * 2) = v;
        }
    }
}

extern "C" void kernel_launch(void* const* d_in, const int* in_sizes, int n_in,
                              void* d_out, int out_size)
{
    const float* feats = (const float*)d_in[0];
    const int*   aff   = (const int*)  d_in[1];
    const float* locs  = (const float*)d_in[2];
    const float* Wt    = (const float*)d_in[3];
    const float* bias  = (const float*)d_in[4];
    float*       out   = (float*)d_out;

    k_convert<<<(NG * MPTS * CIN / 4 + NTH - 1) / NTH, NTH>>>(feats);
    k_locfeat<<<(NG * MPTS + NTH - 1) / NTH, NTH>>>(aff, locs);
    k_fragW<<<(NCHUNK * 2048 + NTH - 1) / NTH, NTH>>>(Wt);

    cudaFuncSetAttribute(affconv_main,
                         cudaFuncAttributeMaxDynamicSharedMemorySize, SMEM_MAIN);
    dim3 grid((MPTS + BM - 1) / BM, NG);
    affconv_main<<<grid, NTH, SMEM_MAIN>>>(aff, bias, out);
}